// round 6
// baseline (speedup 1.0000x reference)
#include <cuda_runtime.h>
#include <cuda_bf16.h>
#include <cstdint>
#include <cstring>

// DotProductAttention B=64,S=1024,D=64 fp32, 1-D valid_lens.
// HMMA bf16-split flash attention, round 5:
//  - softmax (MUFU exp + split) software-pipelined INTO the QK/PV HMMA
//    streams: no serialized MUFU clump between the GEMMs
//  - c-outer QK (8 chains), kc-outer PV, ldmatrix.x4, double-buffered smem

#define BATCH 64
#define SEQ   1024
#define DIM   64
#define TM    128
#define TN    64
#define NTH   256
#define LDS_  72

#define ABYTES   9216u
#define BUFBYTES 36864u
#define SMEMB    73728

static __device__ __forceinline__ void split2(float x0, float x1,
                                              uint32_t& hw, uint32_t& lw) {
    __nv_bfloat162 h = __floats2bfloat162_rn(x0, x1);
    memcpy(&hw, &h, 4);
    float h0 = __uint_as_float(hw << 16);
    float h1 = __uint_as_float(hw & 0xffff0000u);
    __nv_bfloat162 l = __floats2bfloat162_rn(x0 - h0, x1 - h1);
    memcpy(&lw, &l, 4);
}

static __device__ __forceinline__ void mma16816(float* c, const uint32_t* a,
                                                uint32_t b0, uint32_t b1) {
    asm volatile(
        "mma.sync.aligned.m16n8k16.row.col.f32.bf16.bf16.f32 "
        "{%0,%1,%2,%3}, {%4,%5,%6,%7}, {%8,%9}, {%0,%1,%2,%3};"
        : "+f"(c[0]), "+f"(c[1]), "+f"(c[2]), "+f"(c[3])
        : "r"(a[0]), "r"(a[1]), "r"(a[2]), "r"(a[3]), "r"(b0), "r"(b1));
}

static __device__ __forceinline__ void ldsm4(uint32_t& r0, uint32_t& r1,
                                             uint32_t& r2, uint32_t& r3,
                                             uint32_t addr) {
    asm volatile("ldmatrix.sync.aligned.m8n8.x4.shared.b16 {%0,%1,%2,%3}, [%4];"
                 : "=r"(r0), "=r"(r1), "=r"(r2), "=r"(r3) : "r"(addr));
}
static __device__ __forceinline__ void ldsm4t(uint32_t& r0, uint32_t& r1,
                                              uint32_t& r2, uint32_t& r3,
                                              uint32_t addr) {
    asm volatile("ldmatrix.sync.aligned.m8n8.x4.trans.shared.b16 {%0,%1,%2,%3}, [%4];"
                 : "=r"(r0), "=r"(r1), "=r"(r2), "=r"(r3) : "r"(addr));
}

static __device__ __forceinline__ uint32_t smem_u32(const void* p) {
    uint32_t a;
    asm("{ .reg .u64 t; cvta.to.shared.u64 t, %1; cvt.u32.u64 %0, t; }"
        : "=r"(a) : "l"(p));
    return a;
}

__global__ __launch_bounds__(NTH, 1)
void attn_hmma4_kernel(const float* __restrict__ q, const float* __restrict__ k,
                       const float* __restrict__ v, const int* __restrict__ vl,
                       float* __restrict__ out) {
    extern __shared__ char smc[];
    const int tid  = threadIdx.x;
    const int lane = tid & 31;
    const int wid  = tid >> 5;
    const int b    = blockIdx.x >> 3;
    const int qt   = blockIdx.x & 7;
    const int r0   = lane >> 2;
    const int m4   = lane & 3;

    const int  valid  = vl[b];
    const bool uni    = (valid == 0);
    const int  n      = uni ? SEQ : valid;
    const int  ntiles = (n + TN - 1) / TN;

    uint32_t qhi[4][4], qlo[4][4];
    {
        const float* qb = q + ((size_t)(b * SEQ + qt * TM + wid * 16)) * DIM;
        #pragma unroll
        for (int c = 0; c < 4; c++) {
            const int d0 = c * 16 + 2 * m4;
            float2 x00 = *(const float2*)(qb + r0 * DIM + d0);
            float2 x10 = *(const float2*)(qb + (r0 + 8) * DIM + d0);
            float2 x01 = *(const float2*)(qb + r0 * DIM + d0 + 8);
            float2 x11 = *(const float2*)(qb + (r0 + 8) * DIM + d0 + 8);
            split2(x00.x * 0.125f, x00.y * 0.125f, qhi[c][0], qlo[c][0]);
            split2(x10.x * 0.125f, x10.y * 0.125f, qhi[c][1], qlo[c][1]);
            split2(x01.x * 0.125f, x01.y * 0.125f, qhi[c][2], qlo[c][2]);
            split2(x11.x * 0.125f, x11.y * 0.125f, qhi[c][3], qlo[c][3]);
        }
    }

    float oac[8][4];
    #pragma unroll
    for (int g = 0; g < 8; g++)
        oac[g][0] = oac[g][1] = oac[g][2] = oac[g][3] = 0.0f;
    float lr0 = 0.0f, lr1 = 0.0f;

    const float* kb = k + (size_t)b * SEQ * DIM;
    const float* vb = v + (size_t)b * SEQ * DIM;

    const uint32_t sb = smem_u32(smc);
    const uint32_t koff =
        (uint32_t)(((((lane >> 4) & 1) * 8 + (lane & 7)) * LDS_ +
                    ((lane >> 3) & 1) * 8) * 2);
    const uint32_t voff =
        (uint32_t)(((((lane >> 3) & 1) * 8 + (lane & 7)) * LDS_ +
                    ((lane >> 4) & 1) * 8) * 2);

    float4 kr[4], vr[4];

#define LD_REGS(T) do {                                                       \
    const float4* kg4_ = (const float4*)(kb + (size_t)(T) * TN * DIM);        \
    const float4* vg4_ = (const float4*)(vb + (size_t)(T) * TN * DIM);        \
    _Pragma("unroll")                                                         \
    for (int j = 0; j < 4; j++) {                                             \
        kr[j] = __ldg(kg4_ + j * 256 + tid);                                  \
        vr[j] = __ldg(vg4_ + j * 256 + tid);                                  \
    } } while (0)

#define STAGE(BUF) do {                                                       \
    char* base_ = smc + (uint32_t)(BUF) * BUFBYTES;                           \
    _Pragma("unroll")                                                         \
    for (int j = 0; j < 4; j++) {                                             \
        const int i_ = j * 256 + tid;                                         \
        const int off_ = (i_ >> 4) * 144 + (i_ & 15) * 8;                     \
        uint32_t h01_, l01_, h23_, l23_;                                      \
        split2(kr[j].x, kr[j].y, h01_, l01_);                                 \
        split2(kr[j].z, kr[j].w, h23_, l23_);                                 \
        *(uint2*)(base_ + off_)          = make_uint2(h01_, h23_);            \
        *(uint2*)(base_ + ABYTES + off_) = make_uint2(l01_, l23_);            \
        split2(vr[j].x, vr[j].y, h01_, l01_);                                 \
        split2(vr[j].z, vr[j].w, h23_, l23_);                                 \
        *(uint2*)(base_ + 2 * ABYTES + off_) = make_uint2(h01_, h23_);        \
        *(uint2*)(base_ + 3 * ABYTES + off_) = make_uint2(l01_, l23_);        \
    } } while (0)

    LD_REGS(0);
    STAGE(0);
    if (ntiles > 1) LD_REGS(1);
    __syncthreads();

    for (int t = 0; t < ntiles; t++) {
        if (t + 1 < ntiles) STAGE((t + 1) & 1);
        if (t + 2 < ntiles) LD_REGS(t + 2);

        const uint32_t kh = sb + (uint32_t)(t & 1) * BUFBYTES + koff;
        const uint32_t vh = sb + (uint32_t)(t & 1) * BUFBYTES + 2 * ABYTES + voff;

        const int  jt    = t * TN;
        const bool fullt = !uni && (jt + TN <= n);

        float sa[8][4];
        #pragma unroll
        for (int g = 0; g < 8; g++)
            sa[g][0] = sa[g][1] = sa[g][2] = sa[g][3] = 0.0f;
        uint32_t PH[8][2], PL[8][2];

        // softmax for one score group g (4 exps + hi/lo split)
#define SOFTMAX_G(g) do {                                                     \
        float p0_, p1_, p2_, p3_;                                             \
        if (fullt) {                                                          \
            p0_ = __expf(sa[g][0]); p1_ = __expf(sa[g][1]);                   \
            p2_ = __expf(sa[g][2]); p3_ = __expf(sa[g][3]);                   \
        } else if (!uni) {                                                    \
            const int j0_ = jt + (g) * 8 + 2 * m4;                            \
            p0_ = (j0_     < n) ? __expf(sa[g][0]) : 0.0f;                    \
            p1_ = (j0_ + 1 < n) ? __expf(sa[g][1]) : 0.0f;                    \
            p2_ = (j0_     < n) ? __expf(sa[g][2]) : 0.0f;                    \
            p3_ = (j0_ + 1 < n) ? __expf(sa[g][3]) : 0.0f;                    \
        } else {                                                              \
            p0_ = p1_ = p2_ = p3_ = 1.0f;                                     \
        }                                                                     \
        lr0 += p0_ + p1_;                                                     \
        lr1 += p2_ + p3_;                                                     \
        split2(p0_, p1_, PH[g][0], PL[g][0]);                                 \
        split2(p2_, p3_, PH[g][1], PL[g][1]);                                 \
    } while (0)

        // QK chunk: one c-step for one gp pair (12 HMMAs)
#define QK_C_GP(c, gp) do {                                                   \
        uint32_t h0_, h1_, h2_, h3_, l0_, l1_, l2_, l3_;                      \
        const uint32_t ka_ = kh + (gp) * 2304 + (c) * 32;                     \
        ldsm4(h0_, h1_, h2_, h3_, ka_);                                       \
        ldsm4(l0_, l1_, l2_, l3_, ka_ + ABYTES);                              \
        mma16816(sa[2 * (gp)],     qhi[c], h0_, h1_);                         \
        mma16816(sa[2 * (gp) + 1], qhi[c], h2_, h3_);                         \
        mma16816(sa[2 * (gp)],     qlo[c], h0_, h1_);                         \
        mma16816(sa[2 * (gp) + 1], qlo[c], h2_, h3_);                         \
        mma16816(sa[2 * (gp)],     qhi[c], l0_, l1_);                         \
        mma16816(sa[2 * (gp) + 1], qhi[c], l2_, l3_);                         \
    } while (0)

        // PV chunk for one kc (24 HMMAs)
#define PV_KC(kc) do {                                                        \
        const uint32_t ah_[4] = {PH[2 * (kc)][0], PH[2 * (kc)][1],            \
                                 PH[2 * (kc) + 1][0], PH[2 * (kc) + 1][1]};   \
        const uint32_t al_[4] = {PL[2 * (kc)][0], PL[2 * (kc)][1],            \
                                 PL[2 * (kc) + 1][0], PL[2 * (kc) + 1][1]};   \
        _Pragma("unroll")                                                     \
        for (int gp_ = 0; gp_ < 4; gp_++) {                                   \
            uint32_t h0_, h1_, h2_, h3_, l0_, l1_, l2_, l3_;                  \
            const uint32_t va_ = vh + (kc) * 2304 + gp_ * 32;                 \
            ldsm4t(h0_, h1_, h2_, h3_, va_);                                  \
            ldsm4t(l0_, l1_, l2_, l3_, va_ + ABYTES);                         \
            mma16816(oac[2 * gp_],     ah_, h0_, h1_);                        \
            mma16816(oac[2 * gp_ + 1], ah_, h2_, h3_);                        \
            mma16816(oac[2 * gp_],     al_, h0_, h1_);                        \
            mma16816(oac[2 * gp_ + 1], al_, h2_, h3_);                        \
            mma16816(oac[2 * gp_],     ah_, l0_, l1_);                        \
            mma16816(oac[2 * gp_ + 1], ah_, l2_, l3_);                        \
        }                                                                     \
    } while (0)

        // ---- Phase A: QK groups 0..3 (gp 0,1), c-outer
        #pragma unroll
        for (int c = 0; c < 4; c++) { QK_C_GP(c, 0); QK_C_GP(c, 1); }

        // ---- Phase B: QK gp 2,3 with phase-A softmax interleaved
        QK_C_GP(0, 2); QK_C_GP(0, 3); SOFTMAX_G(0);
        QK_C_GP(1, 2); QK_C_GP(1, 3); SOFTMAX_G(1);
        QK_C_GP(2, 2); QK_C_GP(2, 3); SOFTMAX_G(2);
        QK_C_GP(3, 2); QK_C_GP(3, 3); SOFTMAX_G(3);

        // ---- Phase C: PV kc 0,1 with softmax of groups 4..7 interleaved
        SOFTMAX_G(4);
        PV_KC(0);
        SOFTMAX_G(5); SOFTMAX_G(6);
        PV_KC(1);
        SOFTMAX_G(7);

        // ---- Phase D: PV kc 2,3
        PV_KC(2);
        PV_KC(3);

        __syncthreads();
#undef SOFTMAX_G
#undef QK_C_GP
#undef PV_KC
    }

    // ---- epilogue
    lr0 += __shfl_xor_sync(0xffffffffu, lr0, 1);
    lr0 += __shfl_xor_sync(0xffffffffu, lr0, 2);
    lr1 += __shfl_xor_sync(0xffffffffu, lr1, 1);
    lr1 += __shfl_xor_sync(0xffffffffu, lr1, 2);
    const float inv0 = 1.0f / lr0;
    const float inv1 = 1.0f / lr1;

    float* ob = out + ((size_t)(b * SEQ + qt * TM + wid * 16)) * DIM;
    #pragma unroll
    for (int g = 0; g < 8; g++) {
        const int d0 = g * 8 + 2 * m4;
        *(float2*)(ob + r0 * DIM + d0) =
            make_float2(oac[g][0] * inv0, oac[g][1] * inv0);
        *(float2*)(ob + (r0 + 8) * DIM + d0) =
            make_float2(oac[g][2] * inv1, oac[g][3] * inv1);
    }
}

extern "C" void kernel_launch(void* const* d_in, const int* in_sizes, int n_in,
                              void* d_out, int out_size) {
    const float* q  = (const float*)d_in[0];
    const float* k  = (const float*)d_in[1];
    const float* v  = (const float*)d_in[2];
    const int*   vl = (const int*)d_in[3];
    float*       o  = (float*)d_out;

    cudaFuncSetAttribute(attn_hmma4_kernel,
                         cudaFuncAttributeMaxDynamicSharedMemorySize, SMEMB);
    attn_hmma4_kernel<<<BATCH * (SEQ / TM), NTH, SMEMB>>>(q, k, v, vl, o);
}

// round 7
// speedup vs baseline: 1.0429x; 1.0429x over previous
#include <cuda_runtime.h>
#include <cuda_bf16.h>
#include <cstdint>
#include <cstring>

// DotProductAttention B=64,S=1024,D=64 fp32, 1-D valid_lens.
// HMMA bf16-split flash attention, round 6:
//  - all-8-chain round-robin MMA ordering (same-accumulator distance = 8
//    instructions >= HMMA accumulate latency) in both GEMMs
//  - fragments for all 4 gp groups batch-loaded (8 ldmatrix.x4) per k-chunk
//  - round-4 softmax block (interleave experiment regressed; reverted)

#define BATCH 64
#define SEQ   1024
#define DIM   64
#define TM    128
#define TN    64
#define NTH   256
#define LDS_  72

#define ABYTES   9216u
#define BUFBYTES 36864u
#define SMEMB    73728

static __device__ __forceinline__ void split2(float x0, float x1,
                                              uint32_t& hw, uint32_t& lw) {
    __nv_bfloat162 h = __floats2bfloat162_rn(x0, x1);
    memcpy(&hw, &h, 4);
    float h0 = __uint_as_float(hw << 16);
    float h1 = __uint_as_float(hw & 0xffff0000u);
    __nv_bfloat162 l = __floats2bfloat162_rn(x0 - h0, x1 - h1);
    memcpy(&lw, &l, 4);
}

static __device__ __forceinline__ void mma16816(float* c, const uint32_t* a,
                                                uint32_t b0, uint32_t b1) {
    asm volatile(
        "mma.sync.aligned.m16n8k16.row.col.f32.bf16.bf16.f32 "
        "{%0,%1,%2,%3}, {%4,%5,%6,%7}, {%8,%9}, {%0,%1,%2,%3};"
        : "+f"(c[0]), "+f"(c[1]), "+f"(c[2]), "+f"(c[3])
        : "r"(a[0]), "r"(a[1]), "r"(a[2]), "r"(a[3]), "r"(b0), "r"(b1));
}

static __device__ __forceinline__ void ldsm4(uint32_t* r, uint32_t addr) {
    asm volatile("ldmatrix.sync.aligned.m8n8.x4.shared.b16 {%0,%1,%2,%3}, [%4];"
                 : "=r"(r[0]), "=r"(r[1]), "=r"(r[2]), "=r"(r[3]) : "r"(addr));
}
static __device__ __forceinline__ void ldsm4t(uint32_t* r, uint32_t addr) {
    asm volatile("ldmatrix.sync.aligned.m8n8.x4.trans.shared.b16 {%0,%1,%2,%3}, [%4];"
                 : "=r"(r[0]), "=r"(r[1]), "=r"(r[2]), "=r"(r[3]) : "r"(addr));
}

static __device__ __forceinline__ uint32_t smem_u32(const void* p) {
    uint32_t a;
    asm("{ .reg .u64 t; cvta.to.shared.u64 t, %1; cvt.u32.u64 %0, t; }"
        : "=r"(a) : "l"(p));
    return a;
}

__global__ __launch_bounds__(NTH, 1)
void attn_hmma5_kernel(const float* __restrict__ q, const float* __restrict__ k,
                       const float* __restrict__ v, const int* __restrict__ vl,
                       float* __restrict__ out) {
    extern __shared__ char smc[];
    const int tid  = threadIdx.x;
    const int lane = tid & 31;
    const int wid  = tid >> 5;
    const int b    = blockIdx.x >> 3;
    const int qt   = blockIdx.x & 7;
    const int r0   = lane >> 2;
    const int m4   = lane & 3;

    const int  valid  = vl[b];
    const bool uni    = (valid == 0);
    const int  n      = uni ? SEQ : valid;
    const int  ntiles = (n + TN - 1) / TN;

    uint32_t qhi[4][4], qlo[4][4];
    {
        const float* qb = q + ((size_t)(b * SEQ + qt * TM + wid * 16)) * DIM;
        #pragma unroll
        for (int c = 0; c < 4; c++) {
            const int d0 = c * 16 + 2 * m4;
            float2 x00 = *(const float2*)(qb + r0 * DIM + d0);
            float2 x10 = *(const float2*)(qb + (r0 + 8) * DIM + d0);
            float2 x01 = *(const float2*)(qb + r0 * DIM + d0 + 8);
            float2 x11 = *(const float2*)(qb + (r0 + 8) * DIM + d0 + 8);
            split2(x00.x * 0.125f, x00.y * 0.125f, qhi[c][0], qlo[c][0]);
            split2(x10.x * 0.125f, x10.y * 0.125f, qhi[c][1], qlo[c][1]);
            split2(x01.x * 0.125f, x01.y * 0.125f, qhi[c][2], qlo[c][2]);
            split2(x11.x * 0.125f, x11.y * 0.125f, qhi[c][3], qlo[c][3]);
        }
    }

    float oac[8][4];
    #pragma unroll
    for (int g = 0; g < 8; g++)
        oac[g][0] = oac[g][1] = oac[g][2] = oac[g][3] = 0.0f;
    float lr0 = 0.0f, lr1 = 0.0f;

    const float* kb = k + (size_t)b * SEQ * DIM;
    const float* vb = v + (size_t)b * SEQ * DIM;

    const uint32_t sb = smem_u32(smc);
    const uint32_t koff =
        (uint32_t)(((((lane >> 4) & 1) * 8 + (lane & 7)) * LDS_ +
                    ((lane >> 3) & 1) * 8) * 2);
    const uint32_t voff =
        (uint32_t)(((((lane >> 3) & 1) * 8 + (lane & 7)) * LDS_ +
                    ((lane >> 4) & 1) * 8) * 2);

    float4 kr[4], vr[4];

#define LD_REGS(T) do {                                                       \
    const float4* kg4_ = (const float4*)(kb + (size_t)(T) * TN * DIM);        \
    const float4* vg4_ = (const float4*)(vb + (size_t)(T) * TN * DIM);        \
    _Pragma("unroll")                                                         \
    for (int j = 0; j < 4; j++) {                                             \
        kr[j] = __ldg(kg4_ + j * 256 + tid);                                  \
        vr[j] = __ldg(vg4_ + j * 256 + tid);                                  \
    } } while (0)

#define STAGE(BUF) do {                                                       \
    char* base_ = smc + (uint32_t)(BUF) * BUFBYTES;                           \
    _Pragma("unroll")                                                         \
    for (int j = 0; j < 4; j++) {                                             \
        const int i_ = j * 256 + tid;                                         \
        const int off_ = (i_ >> 4) * 144 + (i_ & 15) * 8;                     \
        uint32_t h01_, l01_, h23_, l23_;                                      \
        split2(kr[j].x, kr[j].y, h01_, l01_);                                 \
        split2(kr[j].z, kr[j].w, h23_, l23_);                                 \
        *(uint2*)(base_ + off_)          = make_uint2(h01_, h23_);            \
        *(uint2*)(base_ + ABYTES + off_) = make_uint2(l01_, l23_);            \
        split2(vr[j].x, vr[j].y, h01_, l01_);                                 \
        split2(vr[j].z, vr[j].w, h23_, l23_);                                 \
        *(uint2*)(base_ + 2 * ABYTES + off_) = make_uint2(h01_, h23_);        \
        *(uint2*)(base_ + 3 * ABYTES + off_) = make_uint2(l01_, l23_);        \
    } } while (0)

    LD_REGS(0);
    STAGE(0);
    if (ntiles > 1) LD_REGS(1);
    __syncthreads();

    for (int t = 0; t < ntiles; t++) {
        if (t + 1 < ntiles) STAGE((t + 1) & 1);
        if (t + 2 < ntiles) LD_REGS(t + 2);

        const uint32_t kh = sb + (uint32_t)(t & 1) * BUFBYTES + koff;
        const uint32_t vh = sb + (uint32_t)(t & 1) * BUFBYTES + 2 * ABYTES + voff;

        // ---- QK^T: per c-chunk, batch-load all 4 gp fragment sets, then
        //      3 passes x 8 chains (same-accumulator distance = 8 MMAs)
        float sa[8][4];
        #pragma unroll
        for (int g = 0; g < 8; g++)
            sa[g][0] = sa[g][1] = sa[g][2] = sa[g][3] = 0.0f;
        #pragma unroll
        for (int c = 0; c < 4; c++) {
            uint32_t fh[4][4], fl[4][4];
            #pragma unroll
            for (int gp = 0; gp < 4; gp++) {
                const uint32_t ka = kh + gp * 2304 + c * 32;
                ldsm4(fh[gp], ka);
                ldsm4(fl[gp], ka + ABYTES);
            }
            #pragma unroll
            for (int gp = 0; gp < 4; gp++) {   // pass 1: qhi * khi
                mma16816(sa[2 * gp],     qhi[c], fh[gp][0], fh[gp][1]);
                mma16816(sa[2 * gp + 1], qhi[c], fh[gp][2], fh[gp][3]);
            }
            #pragma unroll
            for (int gp = 0; gp < 4; gp++) {   // pass 2: qlo * khi
                mma16816(sa[2 * gp],     qlo[c], fh[gp][0], fh[gp][1]);
                mma16816(sa[2 * gp + 1], qlo[c], fh[gp][2], fh[gp][3]);
            }
            #pragma unroll
            for (int gp = 0; gp < 4; gp++) {   // pass 3: qhi * klo
                mma16816(sa[2 * gp],     qhi[c], fl[gp][0], fl[gp][1]);
                mma16816(sa[2 * gp + 1], qhi[c], fl[gp][2], fl[gp][3]);
            }
        }

        // ---- softmax (no max); masking hoisted to tile granularity
        uint32_t PH[8][2], PL[8][2];
        const int jt = t * TN;
        if (!uni) {
            if (jt + TN <= n) {
                #pragma unroll
                for (int g = 0; g < 8; g++) {
                    const float p0 = __expf(sa[g][0]);
                    const float p1 = __expf(sa[g][1]);
                    const float p2 = __expf(sa[g][2]);
                    const float p3 = __expf(sa[g][3]);
                    lr0 += p0 + p1;
                    lr1 += p2 + p3;
                    split2(p0, p1, PH[g][0], PL[g][0]);
                    split2(p2, p3, PH[g][1], PL[g][1]);
                }
            } else {
                #pragma unroll
                for (int g = 0; g < 8; g++) {
                    const int j0 = jt + g * 8 + 2 * m4;
                    const float p0 = (j0     < n) ? __expf(sa[g][0]) : 0.0f;
                    const float p1 = (j0 + 1 < n) ? __expf(sa[g][1]) : 0.0f;
                    const float p2 = (j0     < n) ? __expf(sa[g][2]) : 0.0f;
                    const float p3 = (j0 + 1 < n) ? __expf(sa[g][3]) : 0.0f;
                    lr0 += p0 + p1;
                    lr1 += p2 + p3;
                    split2(p0, p1, PH[g][0], PL[g][0]);
                    split2(p2, p3, PH[g][1], PL[g][1]);
                }
            }
        } else {
            #pragma unroll
            for (int g = 0; g < 8; g++) {
                lr0 += 2.0f;
                lr1 += 2.0f;
                PH[g][0] = PH[g][1] = 0x3F803F80u;
                PL[g][0] = PL[g][1] = 0u;
            }
        }

        // ---- P @ V: per kc-chunk, batch-load all 4 gp V fragment sets,
        //      then 3 passes x 8 chains
        #pragma unroll
        for (int kc = 0; kc < 4; kc++) {
            uint32_t fh[4][4], fl[4][4];
            #pragma unroll
            for (int gp = 0; gp < 4; gp++) {
                const uint32_t va = vh + kc * 2304 + gp * 32;
                ldsm4t(fh[gp], va);
                ldsm4t(fl[gp], va + ABYTES);
            }
            const uint32_t ah[4] = {PH[2 * kc][0], PH[2 * kc][1],
                                    PH[2 * kc + 1][0], PH[2 * kc + 1][1]};
            const uint32_t al[4] = {PL[2 * kc][0], PL[2 * kc][1],
                                    PL[2 * kc + 1][0], PL[2 * kc + 1][1]};
            #pragma unroll
            for (int gp = 0; gp < 4; gp++) {   // pass 1: ph * vhi
                mma16816(oac[2 * gp],     ah, fh[gp][0], fh[gp][1]);
                mma16816(oac[2 * gp + 1], ah, fh[gp][2], fh[gp][3]);
            }
            #pragma unroll
            for (int gp = 0; gp < 4; gp++) {   // pass 2: pl * vhi
                mma16816(oac[2 * gp],     al, fh[gp][0], fh[gp][1]);
                mma16816(oac[2 * gp + 1], al, fh[gp][2], fh[gp][3]);
            }
            #pragma unroll
            for (int gp = 0; gp < 4; gp++) {   // pass 3: ph * vlo
                mma16816(oac[2 * gp],     ah, fl[gp][0], fl[gp][1]);
                mma16816(oac[2 * gp + 1], ah, fl[gp][2], fl[gp][3]);
            }
        }
        __syncthreads();
    }

    // ---- epilogue
    lr0 += __shfl_xor_sync(0xffffffffu, lr0, 1);
    lr0 += __shfl_xor_sync(0xffffffffu, lr0, 2);
    lr1 += __shfl_xor_sync(0xffffffffu, lr1, 1);
    lr1 += __shfl_xor_sync(0xffffffffu, lr1, 2);
    const float inv0 = 1.0f / lr0;
    const float inv1 = 1.0f / lr1;

    float* ob = out + ((size_t)(b * SEQ + qt * TM + wid * 16)) * DIM;
    #pragma unroll
    for (int g = 0; g < 8; g++) {
        const int d0 = g * 8 + 2 * m4;
        *(float2*)(ob + r0 * DIM + d0) =
            make_float2(oac[g][0] * inv0, oac[g][1] * inv0);
        *(float2*)(ob + (r0 + 8) * DIM + d0) =
            make_float2(oac[g][2] * inv1, oac[g][3] * inv1);
    }
}

extern "C" void kernel_launch(void* const* d_in, const int* in_sizes, int n_in,
                              void* d_out, int out_size) {
    const float* q  = (const float*)d_in[0];
    const float* k  = (const float*)d_in[1];
    const float* v  = (const float*)d_in[2];
    const int*   vl = (const int*)d_in[3];
    float*       o  = (float*)d_out;

    cudaFuncSetAttribute(attn_hmma5_kernel,
                         cudaFuncAttributeMaxDynamicSharedMemorySize, SMEMB);
    attn_hmma5_kernel<<<BATCH * (SEQ / TM), NTH, SMEMB>>>(q, k, v, vl, o);
}